// round 9
// baseline (speedup 1.0000x reference)
#include <cuda_runtime.h>
#include <math.h>

#define TT 6
#define NN 50000
#define EE 800000
#define FF 32
#define HH 64
#define OUTC 16
#define SPAD 68

#define TOTN (TT * NN)                 // 300000
#define SCAN_BLOCKS 1172               // ceil(TOTN/256)
#define AUX_PER_THREAD 5               // 256*5 = 1280 >= 1172
#define DEG_BPS   3125                 // EE/256
#define PLACE_BPS 3125
#define GATH_BPS  9375                 // TOTN*8/256

typedef unsigned long long u64;
#define FMA_F32X2(d, a, b, c) \
    asm("fma.rn.f32x2 %0, %1, %2, %3;" : "=l"(d) : "l"(a), "l"(b), "l"(c))

// ---------------- scratch (device globals; no allocation allowed) ----------
__device__ __align__(16) float g_aggx[(size_t)TT * NN * FF];  // A_hat@X, all steps
__device__ __align__(16) float g_h   [(size_t)NN * HH];
__device__ int   g_deg [TOTN];
__device__ int   g_roff[TOTN];
__device__ int   g_cur [TOTN];
__device__ int   g_bsum[SCAN_BLOCKS];
__device__ int   g_csr [(size_t)TT * EE];
__device__ float g_dinv[TOTN];

// folded weights, entries DUPLICATED as (w,w) pairs for f32x2 FFMA2
__device__ __align__(16) float g_MtD [3][HH][FF * 2];  // (W @ L_top)^T dup
__device__ __align__(16) float g_LbtD[3][HH][HH * 2];  // L_bot^T dup
__device__ float g_bv[3][HH];

__device__ __forceinline__ float sigmoidf_(float x) {
    return 1.0f / (1.0f + __expf(-x));
}

// ---------------- prep / clears ---------------------------------------------

__global__ void k_clear_h() {
    unsigned idx = blockIdx.x * blockDim.x + threadIdx.x;
    if (idx < (unsigned)(NN * HH)) g_h[idx] = 0.0f;
}

__global__ void k_clear_int2() {
    unsigned i = blockIdx.x * blockDim.x + threadIdx.x;
    if (i < (unsigned)TOTN) { g_deg[i] = 0; g_cur[i] = 0; }
}

__global__ void k_prep(const float* __restrict__ Wz, const float* __restrict__ bz,
                       const float* __restrict__ Wr, const float* __restrict__ br,
                       const float* __restrict__ Wh, const float* __restrict__ bh,
                       const float* __restrict__ Lz, const float* __restrict__ Lzb,
                       const float* __restrict__ Lr, const float* __restrict__ Lrb,
                       const float* __restrict__ Lh, const float* __restrict__ Lhb) {
    int g = blockIdx.x;
    int t = threadIdx.x;
    const float* W  = (g == 0) ? Wz  : (g == 1) ? Wr  : Wh;
    const float* b  = (g == 0) ? bz  : (g == 1) ? br  : bh;
    const float* L  = (g == 0) ? Lz  : (g == 1) ? Lr  : Lh;
    const float* Lb = (g == 0) ? Lzb : (g == 1) ? Lrb : Lhb;

    for (int e = t; e < HH * FF; e += 256) {
        int j = e >> 5, f = e & 31;
        float s = 0.f;
        #pragma unroll 8
        for (int m = 0; m < HH; m++) s += __ldg(W + f * HH + m) * __ldg(L + m * HH + j);
        g_MtD[g][j][2 * f]     = s;
        g_MtD[g][j][2 * f + 1] = s;
    }
    for (int e = t; e < HH * HH; e += 256) {
        int j = e >> 6, k = e & 63;
        float v = __ldg(L + (HH + k) * HH + j);
        g_LbtD[g][j][2 * k]     = v;
        g_LbtD[g][j][2 * k + 1] = v;
    }
    if (t < HH) {
        float sb = __ldg(Lb + t);
        #pragma unroll 8
        for (int m = 0; m < HH; m++) sb += __ldg(b + m) * __ldg(L + m * HH + t);
        g_bv[g][t] = sb;
    }
}

// ---------------- degree + dinv ----------------------------------------------

__global__ void k_deg_all(const int* __restrict__ ei) {
    int t = blockIdx.x / DEG_BPS;
    unsigned e = (blockIdx.x % DEG_BPS) * 256 + threadIdx.x;
    int d = __ldg(ei + (size_t)t * 2 * EE + EE + e);
    atomicAdd(&g_deg[t * NN + d], 1);
}

__global__ void k_dinv_all() {
    unsigned i = blockIdx.x * blockDim.x + threadIdx.x;
    if (i < (unsigned)TOTN) g_dinv[i] = rsqrtf((float)(g_deg[i] + 1));
}

// ---------------- exclusive scan ----------------------------------------------

__global__ void k_scan_block() {
    __shared__ int sh[256];
    int tid = threadIdx.x;
    int i = blockIdx.x * 256 + tid;
    int v = (i < TOTN) ? g_deg[i] : 0;
    sh[tid] = v;
    __syncthreads();
    #pragma unroll
    for (int off = 1; off < 256; off <<= 1) {
        int tv = (tid >= off) ? sh[tid - off] : 0;
        __syncthreads();
        sh[tid] += tv;
        __syncthreads();
    }
    if (i < TOTN) g_roff[i] = sh[tid] - v;
    if (tid == 255) g_bsum[blockIdx.x] = sh[255];
}

__global__ void k_scan_aux() {
    __shared__ int part[256];
    int tid = threadIdx.x;
    int start = tid * AUX_PER_THREAD;
    int loc[AUX_PER_THREAD];
    int vv [AUX_PER_THREAD];
    int sum = 0;
    #pragma unroll
    for (int j = 0; j < AUX_PER_THREAD; j++) {
        int idx = start + j;
        int v = (idx < SCAN_BLOCKS) ? g_bsum[idx] : 0;
        vv[j] = v;
        sum += v;
        loc[j] = sum;
    }
    part[tid] = sum;
    __syncthreads();
    #pragma unroll
    for (int off = 1; off < 256; off <<= 1) {
        int tv = (tid >= off) ? part[tid - off] : 0;
        __syncthreads();
        part[tid] += tv;
        __syncthreads();
    }
    int prev = (tid > 0) ? part[tid - 1] : 0;
    #pragma unroll
    for (int j = 0; j < AUX_PER_THREAD; j++) {
        int idx = start + j;
        if (idx < SCAN_BLOCKS) g_bsum[idx] = prev + loc[j] - vv[j];
    }
}

__global__ void k_scan_add() {
    int i = blockIdx.x * 256 + threadIdx.x;
    if (i < TOTN) g_roff[i] += g_bsum[blockIdx.x];
}

// ---------------- CSR placement ----------------------------------------------

__global__ void k_place(const int* __restrict__ ei) {
    int t = blockIdx.x / PLACE_BPS;
    unsigned e = (blockIdx.x % PLACE_BPS) * 256 + threadIdx.x;
    const int* base = ei + (size_t)t * 2 * EE;
    int s = __ldg(base + e);
    int d = __ldg(base + EE + e);
    int i = t * NN + d;
    int pos = g_roff[i] + atomicAdd(&g_cur[i], 1);
    g_csr[pos] = s;
}

// ---------------- pull-mode gather (R5 version, unchanged) ------------------

__global__ void k_gather(const float* __restrict__ xs) {
    unsigned idx = blockIdx.x * 256 + threadIdx.x;   // < TOTN*8
    unsigned nf = idx >> 3;          // flat (t,node)
    unsigned c  = idx & 7u;
    int t = nf / NN;
    int node = nf - t * NN;
    const float* x = xs + (size_t)t * NN * FF;

    float dd = g_dinv[nf];
    float4 acc = __ldg(reinterpret_cast<const float4*>(x + (size_t)node * FF) + c);
    float d2 = dd * dd;
    acc.x *= d2; acc.y *= d2; acc.z *= d2; acc.w *= d2;

    int beg = g_roff[nf];
    int end = beg + g_deg[nf];
    const float* dinv_t = g_dinv + t * NN;
    for (int p = beg; p < end; p++) {
        int s = __ldg(g_csr + p);
        float ns = dd * __ldg(dinv_t + s);
        float4 v = __ldg(reinterpret_cast<const float4*>(x + (size_t)s * FF) + c);
        acc.x = fmaf(v.x, ns, acc.x);
        acc.y = fmaf(v.y, ns, acc.y);
        acc.z = fmaf(v.z, ns, acc.z);
        acc.w = fmaf(v.w, ns, acc.w);
    }
    reinterpret_cast<float4*>(g_aggx + (size_t)nf * FF)[c] = acc;
}

// ---------------- fused projection + GRU gates (f32x2 / FFMA2) --------------
// Identical structure to the R5 gates; only the FMA stream is packed as
// f32x2 over node-pairs (accumulator = 2 adjacent nodes).

__global__ void __launch_bounds__(256) k_gates2(int t) {
    __shared__ float ag_sh[FF][SPAD];
    __shared__ float h_sh [HH][SPAD];
    __shared__ float hr_sh[HH][SPAD];

    int tid = threadIdx.x;
    int block_base = blockIdx.x * 64;
    const float* aggx_t = g_aggx + (size_t)t * NN * FF;

    #pragma unroll
    for (int r = 0; r < 2; r++) {
        int idx = r * 256 + tid;
        int n = idx >> 3, k4 = idx & 7;
        int node = block_base + n;
        float4 v = make_float4(0.f, 0.f, 0.f, 0.f);
        if (node < NN) v = __ldg(reinterpret_cast<const float4*>(aggx_t + (size_t)node * FF) + k4);
        ag_sh[k4 * 4 + 0][n] = v.x;
        ag_sh[k4 * 4 + 1][n] = v.y;
        ag_sh[k4 * 4 + 2][n] = v.z;
        ag_sh[k4 * 4 + 3][n] = v.w;
    }
    #pragma unroll
    for (int r = 0; r < 4; r++) {
        int idx = r * 256 + tid;
        int n = idx >> 4, k4 = idx & 15;
        int node = block_base + n;
        float4 v = make_float4(0.f, 0.f, 0.f, 0.f);
        if (node < NN) v = __ldg(reinterpret_cast<const float4*>(g_h + (size_t)node * HH) + k4);
        h_sh[k4 * 4 + 0][n] = v.x;
        h_sh[k4 * 4 + 1][n] = v.y;
        h_sh[k4 * 4 + 2][n] = v.z;
        h_sh[k4 * 4 + 3][n] = v.w;
    }
    __syncthreads();

    int warp = tid >> 5, lane = tid & 31;
    int nb = warp * 8;
    int j0 = lane, j1 = lane + 32;

    u64 az0[4], az1[4], ar0[4], ar1[4];
    #pragma unroll
    for (int q = 0; q < 4; q++) { az0[q] = az1[q] = ar0[q] = ar1[q] = 0ULL; }

    // z/r over aggx (FF ks) — duplicated weights: float4 covers 2 ks
    #pragma unroll
    for (int k2 = 0; k2 < FF / 2; k2++) {
        float4 wz0v = __ldg(reinterpret_cast<const float4*>(&g_MtD[0][j0][k2 * 4]));
        float4 wz1v = __ldg(reinterpret_cast<const float4*>(&g_MtD[0][j1][k2 * 4]));
        float4 wr0v = __ldg(reinterpret_cast<const float4*>(&g_MtD[1][j0][k2 * 4]));
        float4 wr1v = __ldg(reinterpret_cast<const float4*>(&g_MtD[1][j1][k2 * 4]));
        const u64* wz0p = (const u64*)&wz0v; const u64* wz1p = (const u64*)&wz1v;
        const u64* wr0p = (const u64*)&wr0v; const u64* wr1p = (const u64*)&wr1v;
        #pragma unroll
        for (int kk = 0; kk < 2; kk++) {
            int k = k2 * 2 + kk;
            const u64* a01 = (const u64*)&ag_sh[k][nb];
            const u64* a23 = (const u64*)&ag_sh[k][nb + 4];
            u64 aa[4] = {a01[0], a01[1], a23[0], a23[1]};
            #pragma unroll
            for (int q = 0; q < 4; q++) {
                FMA_F32X2(az0[q], aa[q], wz0p[kk], az0[q]);
                FMA_F32X2(az1[q], aa[q], wz1p[kk], az1[q]);
                FMA_F32X2(ar0[q], aa[q], wr0p[kk], ar0[q]);
                FMA_F32X2(ar1[q], aa[q], wr1p[kk], ar1[q]);
            }
        }
    }
    // z/r over h (HH ks)
    #pragma unroll
    for (int k2 = 0; k2 < HH / 2; k2++) {
        float4 wz0v = __ldg(reinterpret_cast<const float4*>(&g_LbtD[0][j0][k2 * 4]));
        float4 wz1v = __ldg(reinterpret_cast<const float4*>(&g_LbtD[0][j1][k2 * 4]));
        float4 wr0v = __ldg(reinterpret_cast<const float4*>(&g_LbtD[1][j0][k2 * 4]));
        float4 wr1v = __ldg(reinterpret_cast<const float4*>(&g_LbtD[1][j1][k2 * 4]));
        const u64* wz0p = (const u64*)&wz0v; const u64* wz1p = (const u64*)&wz1v;
        const u64* wr0p = (const u64*)&wr0v; const u64* wr1p = (const u64*)&wr1v;
        #pragma unroll
        for (int kk = 0; kk < 2; kk++) {
            int k = k2 * 2 + kk;
            const u64* a01 = (const u64*)&h_sh[k][nb];
            const u64* a23 = (const u64*)&h_sh[k][nb + 4];
            u64 aa[4] = {a01[0], a01[1], a23[0], a23[1]};
            #pragma unroll
            for (int q = 0; q < 4; q++) {
                FMA_F32X2(az0[q], aa[q], wz0p[kk], az0[q]);
                FMA_F32X2(az1[q], aa[q], wz1p[kk], az1[q]);
                FMA_F32X2(ar0[q], aa[q], wr0p[kk], ar0[q]);
                FMA_F32X2(ar1[q], aa[q], wr1p[kk], ar1[q]);
            }
        }
    }

    float bvz0 = __ldg(&g_bv[0][j0]), bvz1 = __ldg(&g_bv[0][j1]);
    float bvr0 = __ldg(&g_bv[1][j0]), bvr1 = __ldg(&g_bv[1][j1]);

    float Z0a[8], Z1a[8];
    #pragma unroll
    for (int q = 0; q < 4; q++) {
        float z0lo = __uint_as_float((unsigned)(az0[q] & 0xffffffffULL));
        float z0hi = __uint_as_float((unsigned)(az0[q] >> 32));
        float z1lo = __uint_as_float((unsigned)(az1[q] & 0xffffffffULL));
        float z1hi = __uint_as_float((unsigned)(az1[q] >> 32));
        float r0lo = __uint_as_float((unsigned)(ar0[q] & 0xffffffffULL));
        float r0hi = __uint_as_float((unsigned)(ar0[q] >> 32));
        float r1lo = __uint_as_float((unsigned)(ar1[q] & 0xffffffffULL));
        float r1hi = __uint_as_float((unsigned)(ar1[q] >> 32));
        int n0 = q * 2, n1 = q * 2 + 1;
        Z0a[n0] = sigmoidf_(z0lo + bvz0);  Z0a[n1] = sigmoidf_(z0hi + bvz0);
        Z1a[n0] = sigmoidf_(z1lo + bvz1);  Z1a[n1] = sigmoidf_(z1hi + bvz1);
        float R00 = sigmoidf_(r0lo + bvr0), R01 = sigmoidf_(r0hi + bvr0);
        float R10 = sigmoidf_(r1lo + bvr1), R11 = sigmoidf_(r1hi + bvr1);
        hr_sh[j0][nb + n0] = h_sh[j0][nb + n0] * R00;
        hr_sh[j0][nb + n1] = h_sh[j0][nb + n1] * R01;
        hr_sh[j1][nb + n0] = h_sh[j1][nb + n0] * R10;
        hr_sh[j1][nb + n1] = h_sh[j1][nb + n1] * R11;
    }
    __syncwarp();

    // h gate
    u64 ah0[4], ah1[4];
    #pragma unroll
    for (int q = 0; q < 4; q++) { ah0[q] = ah1[q] = 0ULL; }

    #pragma unroll
    for (int k2 = 0; k2 < FF / 2; k2++) {
        float4 wh0v = __ldg(reinterpret_cast<const float4*>(&g_MtD[2][j0][k2 * 4]));
        float4 wh1v = __ldg(reinterpret_cast<const float4*>(&g_MtD[2][j1][k2 * 4]));
        const u64* wh0p = (const u64*)&wh0v; const u64* wh1p = (const u64*)&wh1v;
        #pragma unroll
        for (int kk = 0; kk < 2; kk++) {
            int k = k2 * 2 + kk;
            const u64* a01 = (const u64*)&ag_sh[k][nb];
            const u64* a23 = (const u64*)&ag_sh[k][nb + 4];
            u64 aa[4] = {a01[0], a01[1], a23[0], a23[1]};
            #pragma unroll
            for (int q = 0; q < 4; q++) {
                FMA_F32X2(ah0[q], aa[q], wh0p[kk], ah0[q]);
                FMA_F32X2(ah1[q], aa[q], wh1p[kk], ah1[q]);
            }
        }
    }
    #pragma unroll
    for (int k2 = 0; k2 < HH / 2; k2++) {
        float4 wh0v = __ldg(reinterpret_cast<const float4*>(&g_LbtD[2][j0][k2 * 4]));
        float4 wh1v = __ldg(reinterpret_cast<const float4*>(&g_LbtD[2][j1][k2 * 4]));
        const u64* wh0p = (const u64*)&wh0v; const u64* wh1p = (const u64*)&wh1v;
        #pragma unroll
        for (int kk = 0; kk < 2; kk++) {
            int k = k2 * 2 + kk;
            const u64* a01 = (const u64*)&hr_sh[k][nb];
            const u64* a23 = (const u64*)&hr_sh[k][nb + 4];
            u64 aa[4] = {a01[0], a01[1], a23[0], a23[1]};
            #pragma unroll
            for (int q = 0; q < 4; q++) {
                FMA_F32X2(ah0[q], aa[q], wh0p[kk], ah0[q]);
                FMA_F32X2(ah1[q], aa[q], wh1p[kk], ah1[q]);
            }
        }
    }

    float bvh0 = __ldg(&g_bv[2][j0]), bvh1 = __ldg(&g_bv[2][j1]);
    #pragma unroll
    for (int q = 0; q < 4; q++) {
        float h0lo = __uint_as_float((unsigned)(ah0[q] & 0xffffffffULL));
        float h0hi = __uint_as_float((unsigned)(ah0[q] >> 32));
        float h1lo = __uint_as_float((unsigned)(ah1[q] & 0xffffffffULL));
        float h1hi = __uint_as_float((unsigned)(ah1[q] >> 32));
        int nn0 = q * 2, nn1 = q * 2 + 1;
        int node0 = block_base + nb + nn0;
        int node1 = block_base + nb + nn1;
        if (node0 < NN) {
            float Ht0 = tanhf(h0lo + bvh0);
            float Ht1 = tanhf(h1lo + bvh1);
            float h0 = h_sh[j0][nb + nn0];
            float h1 = h_sh[j1][nb + nn0];
            g_h[(size_t)node0 * HH + j0] = Z0a[nn0] * h0 + (1.f - Z0a[nn0]) * Ht0;
            g_h[(size_t)node0 * HH + j1] = Z1a[nn0] * h1 + (1.f - Z1a[nn0]) * Ht1;
        }
        if (node1 < NN) {
            float Ht0 = tanhf(h0hi + bvh0);
            float Ht1 = tanhf(h1hi + bvh1);
            float h0 = h_sh[j0][nb + nn1];
            float h1 = h_sh[j1][nb + nn1];
            g_h[(size_t)node1 * HH + j0] = Z0a[nn1] * h0 + (1.f - Z0a[nn1]) * Ht0;
            g_h[(size_t)node1 * HH + j1] = Z1a[nn1] * h1 + (1.f - Z1a[nn1]) * Ht1;
        }
    }
}

__global__ void k_out(const float* __restrict__ oW, const float* __restrict__ ob,
                      float* __restrict__ out) {
    unsigned idx = blockIdx.x * blockDim.x + threadIdx.x;
    if (idx >= (unsigned)(NN * OUTC)) return;
    int i = idx >> 4, j = idx & 15;
    const float* hr = g_h + (size_t)i * HH;
    float acc = __ldg(ob + j);
    #pragma unroll
    for (int k = 0; k < HH; k++) acc += hr[k] * __ldg(oW + k * OUTC + j);
    out[idx] = acc;
}

// ---------------- launch ----------------------------------------------------
extern "C" void kernel_launch(void* const* d_in, const int* in_sizes, int n_in,
                              void* d_out, int out_size) {
    const float* xs  = (const float*)d_in[0];
    const int*   ei  = (const int*)  d_in[1];
    const float* Wz  = (const float*)d_in[2];
    const float* bz  = (const float*)d_in[3];
    const float* Wr  = (const float*)d_in[4];
    const float* br  = (const float*)d_in[5];
    const float* Wh  = (const float*)d_in[6];
    const float* bh  = (const float*)d_in[7];
    const float* Lz  = (const float*)d_in[8];
    const float* Lzb = (const float*)d_in[9];
    const float* Lr  = (const float*)d_in[10];
    const float* Lrb = (const float*)d_in[11];
    const float* Lh  = (const float*)d_in[12];
    const float* Lhb = (const float*)d_in[13];
    const float* oW  = (const float*)d_in[14];
    const float* ob  = (const float*)d_in[15];
    float* out = (float*)d_out;

    k_prep<<<3, 256>>>(Wz, bz, Wr, br, Wh, bh, Lz, Lzb, Lr, Lrb, Lh, Lhb);
    k_clear_h<<<(NN * HH + 255) / 256, 256>>>();
    k_clear_int2<<<SCAN_BLOCKS, 256>>>();

    k_deg_all<<<TT * DEG_BPS, 256>>>(ei);
    k_dinv_all<<<SCAN_BLOCKS, 256>>>();
    k_scan_block<<<SCAN_BLOCKS, 256>>>();
    k_scan_aux<<<1, 256>>>();
    k_scan_add<<<SCAN_BLOCKS, 256>>>();
    k_place<<<TT * PLACE_BPS, 256>>>(ei);
    k_gather<<<GATH_BPS, 256>>>(xs);

    for (int t = 0; t < TT; t++)
        k_gates2<<<(NN + 63) / 64, 256>>>(t);

    k_out<<<(NN * OUTC + 255) / 256, 256>>>(oW, ob, out);
}

// round 10
// speedup vs baseline: 2.9704x; 2.9704x over previous
#include <cuda_runtime.h>
#include <math.h>

#define TT 6
#define NN 50000
#define EE 800000
#define FF 32
#define HH 64
#define OUTC 16
#define SPAD 68

#define TOTN (TT * NN)                 // 300000
#define SCAN_BLOCKS 1172               // ceil(TOTN/256)
#define AUX_PER_THREAD 5               // 256*5 = 1280 >= 1172
#define DEG_BPS   3125                 // EE/256
#define PLACE_BPS 3125
#define GATH_BPS  9375                 // TOTN*8/256
#define KK 96                          // FF + HH

typedef unsigned long long u64;

// ---------------- scratch (device globals; no allocation allowed) ----------
__device__ __align__(16) float g_aggx[(size_t)TT * NN * FF];  // A_hat@X, all steps
__device__ __align__(16) float g_h   [(size_t)NN * HH];
__device__ int   g_deg [TOTN];
__device__ int   g_roff[TOTN];
__device__ int   g_cur [TOTN];
__device__ int   g_bsum[SCAN_BLOCKS];
__device__ u64   g_csrp[(size_t)TT * EE];   // packed (src, norm) per edge
__device__ float g_dinv[TOTN];

// folded weights, k-major, paired for coalesced float2 loads:
// g_Wk2[g][k][l] = ( Wrow(l)[k], Wrow(l+32)[k] )
//   k <  FF : folded (W @ L_top)^T entry for input feature k
//   k >= FF : L_bot[k-FF][j] entry
__device__ __align__(16) float2 g_Wk2[3][KK][32];
__device__ float g_bv[3][HH];

__device__ __forceinline__ float sigmoidf_(float x) {
    return 1.0f / (1.0f + __expf(-x));
}

// ---------------- prep / clears ---------------------------------------------

__global__ void k_clear_h() {
    unsigned idx = blockIdx.x * blockDim.x + threadIdx.x;
    if (idx < (unsigned)(NN * HH)) g_h[idx] = 0.0f;
}

__global__ void k_clear_int2() {
    unsigned i = blockIdx.x * blockDim.x + threadIdx.x;
    if (i < (unsigned)TOTN) { g_deg[i] = 0; g_cur[i] = 0; }
}

// one block per gate
__global__ void k_prep(const float* __restrict__ Wz, const float* __restrict__ bz,
                       const float* __restrict__ Wr, const float* __restrict__ br,
                       const float* __restrict__ Wh, const float* __restrict__ bh,
                       const float* __restrict__ Lz, const float* __restrict__ Lzb,
                       const float* __restrict__ Lr, const float* __restrict__ Lrb,
                       const float* __restrict__ Lh, const float* __restrict__ Lhb) {
    int g = blockIdx.x;
    int t = threadIdx.x;
    const float* W  = (g == 0) ? Wz  : (g == 1) ? Wr  : Wh;
    const float* b  = (g == 0) ? bz  : (g == 1) ? br  : bh;
    const float* L  = (g == 0) ? Lz  : (g == 1) ? Lr  : Lh;
    const float* Lb = (g == 0) ? Lzb : (g == 1) ? Lrb : Lhb;

    for (int e = t; e < KK * 32; e += 256) {
        int k = e >> 5, l = e & 31;
        float w0, w1;
        if (k < FF) {
            float s0 = 0.f, s1 = 0.f;
            #pragma unroll 8
            for (int m = 0; m < HH; m++) {
                float wv = __ldg(W + k * HH + m);
                s0 += wv * __ldg(L + m * HH + l);
                s1 += wv * __ldg(L + m * HH + l + 32);
            }
            w0 = s0; w1 = s1;
        } else {
            w0 = __ldg(L + (HH + k - FF) * HH + l);
            w1 = __ldg(L + (HH + k - FF) * HH + l + 32);
        }
        g_Wk2[g][k][l] = make_float2(w0, w1);
    }
    if (t < HH) {
        float sb = __ldg(Lb + t);
        #pragma unroll 8
        for (int m = 0; m < HH; m++) sb += __ldg(b + m) * __ldg(L + m * HH + t);
        g_bv[g][t] = sb;
    }
}

// ---------------- degree + dinv ----------------------------------------------

__global__ void k_deg_all(const int* __restrict__ ei) {
    int t = blockIdx.x / DEG_BPS;
    unsigned e = (blockIdx.x % DEG_BPS) * 256 + threadIdx.x;
    int d = __ldg(ei + (size_t)t * 2 * EE + EE + e);
    atomicAdd(&g_deg[t * NN + d], 1);
}

__global__ void k_dinv_all() {
    unsigned i = blockIdx.x * blockDim.x + threadIdx.x;
    if (i < (unsigned)TOTN) g_dinv[i] = rsqrtf((float)(g_deg[i] + 1));
}

// ---------------- exclusive scan ----------------------------------------------

__global__ void k_scan_block() {
    __shared__ int sh[256];
    int tid = threadIdx.x;
    int i = blockIdx.x * 256 + tid;
    int v = (i < TOTN) ? g_deg[i] : 0;
    sh[tid] = v;
    __syncthreads();
    #pragma unroll
    for (int off = 1; off < 256; off <<= 1) {
        int tv = (tid >= off) ? sh[tid - off] : 0;
        __syncthreads();
        sh[tid] += tv;
        __syncthreads();
    }
    if (i < TOTN) g_roff[i] = sh[tid] - v;
    if (tid == 255) g_bsum[blockIdx.x] = sh[255];
}

__global__ void k_scan_aux() {
    __shared__ int part[256];
    int tid = threadIdx.x;
    int start = tid * AUX_PER_THREAD;
    int loc[AUX_PER_THREAD];
    int vv [AUX_PER_THREAD];
    int sum = 0;
    #pragma unroll
    for (int j = 0; j < AUX_PER_THREAD; j++) {
        int idx = start + j;
        int v = (idx < SCAN_BLOCKS) ? g_bsum[idx] : 0;
        vv[j] = v;
        sum += v;
        loc[j] = sum;
    }
    part[tid] = sum;
    __syncthreads();
    #pragma unroll
    for (int off = 1; off < 256; off <<= 1) {
        int tv = (tid >= off) ? part[tid - off] : 0;
        __syncthreads();
        part[tid] += tv;
        __syncthreads();
    }
    int prev = (tid > 0) ? part[tid - 1] : 0;
    #pragma unroll
    for (int j = 0; j < AUX_PER_THREAD; j++) {
        int idx = start + j;
        if (idx < SCAN_BLOCKS) g_bsum[idx] = prev + loc[j] - vv[j];
    }
}

__global__ void k_scan_add() {
    int i = blockIdx.x * 256 + threadIdx.x;
    if (i < TOTN) g_roff[i] += g_bsum[blockIdx.x];
}

// ---------------- CSR placement (packed src + norm) -------------------------

__global__ void k_place(const int* __restrict__ ei) {
    int t = blockIdx.x / PLACE_BPS;
    unsigned e = (blockIdx.x % PLACE_BPS) * 256 + threadIdx.x;
    const int* base = ei + (size_t)t * 2 * EE;
    int s = __ldg(base + e);
    int d = __ldg(base + EE + e);
    int i = t * NN + d;
    int pos = g_roff[i] + atomicAdd(&g_cur[i], 1);
    float w = __ldg(&g_dinv[t * NN + s]) * __ldg(&g_dinv[i]);
    g_csrp[pos] = (u64)(unsigned)s | ((u64)__float_as_uint(w) << 32);
}

// ---------------- pull-mode gather (R5 loop, packed records) ----------------

__global__ void k_gather(const float* __restrict__ xs) {
    unsigned idx = blockIdx.x * 256 + threadIdx.x;   // < TOTN*8
    unsigned nf = idx >> 3;          // flat (t,node)
    unsigned c  = idx & 7u;
    int t = nf / NN;
    int node = nf - t * NN;
    const float* x = xs + (size_t)t * NN * FF;

    float dd = g_dinv[nf];
    float4 acc = __ldg(reinterpret_cast<const float4*>(x + (size_t)node * FF) + c);
    float d2 = dd * dd;
    acc.x *= d2; acc.y *= d2; acc.z *= d2; acc.w *= d2;

    int beg = g_roff[nf];
    int end = beg + g_deg[nf];
    for (int p = beg; p < end; p++) {
        u64 rec = __ldg(g_csrp + p);
        int s = (int)(unsigned)(rec & 0xffffffffULL);
        float ns = __uint_as_float((unsigned)(rec >> 32));
        float4 v = __ldg(reinterpret_cast<const float4*>(x + (size_t)s * FF) + c);
        acc.x = fmaf(v.x, ns, acc.x);
        acc.y = fmaf(v.y, ns, acc.y);
        acc.z = fmaf(v.z, ns, acc.z);
        acc.w = fmaf(v.w, ns, acc.w);
    }
    reinterpret_cast<float4*>(g_aggx + (size_t)nf * FF)[c] = acc;
}

// ---------------- fused projection + GRU gates (coalesced k-major weights) --
// Block = 256 threads = 8 warps = 64 nodes. Warp: 8 nodes; lane owns cols
// j0=lane, j1=lane+32. Weight load per (gate,k): ONE coalesced float2 LDG.

__global__ void __launch_bounds__(256) k_gates2(int t) {
    __shared__ float ag_sh[FF][SPAD];
    __shared__ float h_sh [HH][SPAD];
    __shared__ float hr_sh[HH][SPAD];

    int tid = threadIdx.x;
    int block_base = blockIdx.x * 64;
    const float* aggx_t = g_aggx + (size_t)t * NN * FF;

    #pragma unroll
    for (int r = 0; r < 2; r++) {
        int idx = r * 256 + tid;
        int n = idx >> 3, k4 = idx & 7;
        int node = block_base + n;
        float4 v = make_float4(0.f, 0.f, 0.f, 0.f);
        if (node < NN) v = __ldg(reinterpret_cast<const float4*>(aggx_t + (size_t)node * FF) + k4);
        ag_sh[k4 * 4 + 0][n] = v.x;
        ag_sh[k4 * 4 + 1][n] = v.y;
        ag_sh[k4 * 4 + 2][n] = v.z;
        ag_sh[k4 * 4 + 3][n] = v.w;
    }
    #pragma unroll
    for (int r = 0; r < 4; r++) {
        int idx = r * 256 + tid;
        int n = idx >> 4, k4 = idx & 15;
        int node = block_base + n;
        float4 v = make_float4(0.f, 0.f, 0.f, 0.f);
        if (node < NN) v = __ldg(reinterpret_cast<const float4*>(g_h + (size_t)node * HH) + k4);
        h_sh[k4 * 4 + 0][n] = v.x;
        h_sh[k4 * 4 + 1][n] = v.y;
        h_sh[k4 * 4 + 2][n] = v.z;
        h_sh[k4 * 4 + 3][n] = v.w;
    }
    __syncthreads();

    int warp = tid >> 5, lane = tid & 31;
    int nb = warp * 8;
    int j0 = lane, j1 = lane + 32;

    // ---- z & r gates -------------------------------------------------------
    float az0[8], az1[8], ar0[8], ar1[8];
    #pragma unroll
    for (int n = 0; n < 8; n++) { az0[n] = az1[n] = ar0[n] = ar1[n] = 0.f; }

    #pragma unroll 8
    for (int k = 0; k < FF; k++) {
        float2 wz = __ldg(&g_Wk2[0][k][lane]);
        float2 wr = __ldg(&g_Wk2[1][k][lane]);
        float4 v0 = *reinterpret_cast<const float4*>(&ag_sh[k][nb]);
        float4 v1 = *reinterpret_cast<const float4*>(&ag_sh[k][nb + 4]);
        float aa[8] = {v0.x, v0.y, v0.z, v0.w, v1.x, v1.y, v1.z, v1.w};
        #pragma unroll
        for (int n = 0; n < 8; n++) {
            az0[n] = fmaf(aa[n], wz.x, az0[n]);
            az1[n] = fmaf(aa[n], wz.y, az1[n]);
            ar0[n] = fmaf(aa[n], wr.x, ar0[n]);
            ar1[n] = fmaf(aa[n], wr.y, ar1[n]);
        }
    }
    #pragma unroll 8
    for (int k = 0; k < HH; k++) {
        float2 wz = __ldg(&g_Wk2[0][FF + k][lane]);
        float2 wr = __ldg(&g_Wk2[1][FF + k][lane]);
        float4 v0 = *reinterpret_cast<const float4*>(&h_sh[k][nb]);
        float4 v1 = *reinterpret_cast<const float4*>(&h_sh[k][nb + 4]);
        float aa[8] = {v0.x, v0.y, v0.z, v0.w, v1.x, v1.y, v1.z, v1.w};
        #pragma unroll
        for (int n = 0; n < 8; n++) {
            az0[n] = fmaf(aa[n], wz.x, az0[n]);
            az1[n] = fmaf(aa[n], wz.y, az1[n]);
            ar0[n] = fmaf(aa[n], wr.x, ar0[n]);
            ar1[n] = fmaf(aa[n], wr.y, ar1[n]);
        }
    }

    float bvz0 = __ldg(&g_bv[0][j0]), bvz1 = __ldg(&g_bv[0][j1]);
    float bvr0 = __ldg(&g_bv[1][j0]), bvr1 = __ldg(&g_bv[1][j1]);

    float Z0a[8], Z1a[8];
    #pragma unroll
    for (int n = 0; n < 8; n++) {
        Z0a[n] = sigmoidf_(az0[n] + bvz0);
        Z1a[n] = sigmoidf_(az1[n] + bvz1);
        float R0 = sigmoidf_(ar0[n] + bvr0);
        float R1 = sigmoidf_(ar1[n] + bvr1);
        hr_sh[j0][nb + n] = h_sh[j0][nb + n] * R0;
        hr_sh[j1][nb + n] = h_sh[j1][nb + n] * R1;
    }
    __syncwarp();

    // ---- h gate ------------------------------------------------------------
    float ah0[8], ah1[8];
    #pragma unroll
    for (int n = 0; n < 8; n++) { ah0[n] = ah1[n] = 0.f; }

    #pragma unroll 8
    for (int k = 0; k < FF; k++) {
        float2 wh = __ldg(&g_Wk2[2][k][lane]);
        float4 v0 = *reinterpret_cast<const float4*>(&ag_sh[k][nb]);
        float4 v1 = *reinterpret_cast<const float4*>(&ag_sh[k][nb + 4]);
        float aa[8] = {v0.x, v0.y, v0.z, v0.w, v1.x, v1.y, v1.z, v1.w};
        #pragma unroll
        for (int n = 0; n < 8; n++) {
            ah0[n] = fmaf(aa[n], wh.x, ah0[n]);
            ah1[n] = fmaf(aa[n], wh.y, ah1[n]);
        }
    }
    #pragma unroll 8
    for (int k = 0; k < HH; k++) {
        float2 wh = __ldg(&g_Wk2[2][FF + k][lane]);
        float4 v0 = *reinterpret_cast<const float4*>(&hr_sh[k][nb]);
        float4 v1 = *reinterpret_cast<const float4*>(&hr_sh[k][nb + 4]);
        float aa[8] = {v0.x, v0.y, v0.z, v0.w, v1.x, v1.y, v1.z, v1.w};
        #pragma unroll
        for (int n = 0; n < 8; n++) {
            ah0[n] = fmaf(aa[n], wh.x, ah0[n]);
            ah1[n] = fmaf(aa[n], wh.y, ah1[n]);
        }
    }

    float bvh0 = __ldg(&g_bv[2][j0]), bvh1 = __ldg(&g_bv[2][j1]);
    #pragma unroll
    for (int n = 0; n < 8; n++) {
        int node = block_base + nb + n;
        if (node < NN) {
            float Ht0 = tanhf(ah0[n] + bvh0);
            float Ht1 = tanhf(ah1[n] + bvh1);
            float h0 = h_sh[j0][nb + n];
            float h1 = h_sh[j1][nb + n];
            g_h[(size_t)node * HH + j0] = Z0a[n] * h0 + (1.f - Z0a[n]) * Ht0;
            g_h[(size_t)node * HH + j1] = Z1a[n] * h1 + (1.f - Z1a[n]) * Ht1;
        }
    }
}

__global__ void k_out(const float* __restrict__ oW, const float* __restrict__ ob,
                      float* __restrict__ out) {
    unsigned idx = blockIdx.x * blockDim.x + threadIdx.x;
    if (idx >= (unsigned)(NN * OUTC)) return;
    int i = idx >> 4, j = idx & 15;
    const float* hr = g_h + (size_t)i * HH;
    float acc = __ldg(ob + j);
    #pragma unroll
    for (int k = 0; k < HH; k++) acc += hr[k] * __ldg(oW + k * OUTC + j);
    out[idx] = acc;
}

// ---------------- launch ----------------------------------------------------
extern "C" void kernel_launch(void* const* d_in, const int* in_sizes, int n_in,
                              void* d_out, int out_size) {
    const float* xs  = (const float*)d_in[0];
    const int*   ei  = (const int*)  d_in[1];
    const float* Wz  = (const float*)d_in[2];
    const float* bz  = (const float*)d_in[3];
    const float* Wr  = (const float*)d_in[4];
    const float* br  = (const float*)d_in[5];
    const float* Wh  = (const float*)d_in[6];
    const float* bh  = (const float*)d_in[7];
    const float* Lz  = (const float*)d_in[8];
    const float* Lzb = (const float*)d_in[9];
    const float* Lr  = (const float*)d_in[10];
    const float* Lrb = (const float*)d_in[11];
    const float* Lh  = (const float*)d_in[12];
    const float* Lhb = (const float*)d_in[13];
    const float* oW  = (const float*)d_in[14];
    const float* ob  = (const float*)d_in[15];
    float* out = (float*)d_out;

    k_prep<<<3, 256>>>(Wz, bz, Wr, br, Wh, bh, Lz, Lzb, Lr, Lrb, Lh, Lhb);
    k_clear_h<<<(NN * HH + 255) / 256, 256>>>();
    k_clear_int2<<<SCAN_BLOCKS, 256>>>();

    k_deg_all<<<TT * DEG_BPS, 256>>>(ei);
    k_dinv_all<<<SCAN_BLOCKS, 256>>>();
    k_scan_block<<<SCAN_BLOCKS, 256>>>();
    k_scan_aux<<<1, 256>>>();
    k_scan_add<<<SCAN_BLOCKS, 256>>>();
    k_place<<<TT * PLACE_BPS, 256>>>(ei);
    k_gather<<<GATH_BPS, 256>>>(xs);

    for (int t = 0; t < TT; t++)
        k_gates2<<<(NN + 63) / 64, 256>>>(t);

    k_out<<<(NN * OUTC + 255) / 256, 256>>>(oW, ob, out);
}

// round 11
// speedup vs baseline: 3.1928x; 1.0749x over previous
#include <cuda_runtime.h>
#include <math.h>

#define TT 6
#define NN 50000
#define EE 800000
#define FF 32
#define HH 64
#define OUTC 16

#define TOTN (TT * NN)                 // 300000
#define SCAN_BLOCKS 1172               // ceil(TOTN/256)
#define AUX_PER_THREAD 5               // 256*5 = 1280 >= 1172
#define DEG_BPS   3125                 // EE/256
#define PLACE_BPS 3125
#define GATH_BPS  9375                 // TOTN*8/256
#define KK 96                          // FF + HH

// gate-GEMM (mma) config
#define NPB 128                        // nodes per block (8 warps x 16)
#define GATE_BLOCKS 391                // ceil(NN/128)
#define BSH_W 72                       // Bsh stride (words): 72%32=8 -> conflict-free b-frags
#define HR_W  68                       // HRw stride (words): 68%32=4 -> conflict-free a-frags
#define SMEM_GATES ((KK * BSH_W + 8 * 16 * HR_W) * 4)   // 62464 bytes

typedef unsigned long long u64;

// ---------------- scratch (device globals; no allocation allowed) ----------
__device__ __align__(16) float g_aggx[(size_t)TT * NN * FF];  // A_hat@X, all steps
__device__ __align__(16) float g_h   [(size_t)NN * HH];
__device__ int   g_deg [TOTN];
__device__ int   g_roff[TOTN];
__device__ int   g_cur [TOTN];
__device__ int   g_bsum[SCAN_BLOCKS];
__device__ u64   g_csrp[(size_t)TT * EE];   // packed (src, norm) per edge
__device__ float g_dinv[TOTN];

// folded weights, k-major, pre-converted to tf32 bit patterns:
// g_Wmma[g][k][n]: k<FF -> (W@L_top) fold for feature k; k>=FF -> L_bot[k-FF][n]
__device__ __align__(16) unsigned g_Wmma[3][KK][HH];
__device__ float g_bv[3][HH];

__device__ __forceinline__ float sigmoidf_(float x) {
    return 1.0f / (1.0f + __expf(-x));
}

__device__ __forceinline__ unsigned f2tf(float f) {
    unsigned r; asm("cvt.rna.tf32.f32 %0, %1;" : "=r"(r) : "f"(f)); return r;
}

__device__ __forceinline__ void mma8(float* d,
                                     unsigned a0, unsigned a1, unsigned a2, unsigned a3,
                                     unsigned b0, unsigned b1) {
    asm volatile("mma.sync.aligned.m16n8k8.row.col.f32.tf32.tf32.f32 "
        "{%0,%1,%2,%3}, {%4,%5,%6,%7}, {%8,%9}, {%0,%1,%2,%3};"
        : "+f"(d[0]), "+f"(d[1]), "+f"(d[2]), "+f"(d[3])
        : "r"(a0), "r"(a1), "r"(a2), "r"(a3), "r"(b0), "r"(b1));
}

// ---------------- prep / clears ---------------------------------------------

__global__ void k_clear_h() {
    unsigned idx = blockIdx.x * blockDim.x + threadIdx.x;
    if (idx < (unsigned)(NN * HH)) g_h[idx] = 0.0f;
}

__global__ void k_clear_int2() {
    unsigned i = blockIdx.x * blockDim.x + threadIdx.x;
    if (i < (unsigned)TOTN) { g_deg[i] = 0; g_cur[i] = 0; }
}

// one block per gate: build k-major tf32 weight panel + folded biases
__global__ void k_prep(const float* __restrict__ Wz, const float* __restrict__ bz,
                       const float* __restrict__ Wr, const float* __restrict__ br,
                       const float* __restrict__ Wh, const float* __restrict__ bh,
                       const float* __restrict__ Lz, const float* __restrict__ Lzb,
                       const float* __restrict__ Lr, const float* __restrict__ Lrb,
                       const float* __restrict__ Lh, const float* __restrict__ Lhb) {
    int g = blockIdx.x;
    int t = threadIdx.x;
    const float* W  = (g == 0) ? Wz  : (g == 1) ? Wr  : Wh;
    const float* b  = (g == 0) ? bz  : (g == 1) ? br  : bh;
    const float* L  = (g == 0) ? Lz  : (g == 1) ? Lr  : Lh;
    const float* Lb = (g == 0) ? Lzb : (g == 1) ? Lrb : Lhb;

    for (int e = t; e < KK * HH; e += 256) {
        int k = e >> 6, n = e & 63;
        float w;
        if (k < FF) {
            float s = 0.f;
            #pragma unroll 8
            for (int m = 0; m < HH; m++) s += __ldg(W + k * HH + m) * __ldg(L + m * HH + n);
            w = s;
        } else {
            w = __ldg(L + (k + 32) * HH + n);   // L_bot row (k-FF)+HH = k+32
        }
        g_Wmma[g][k][n] = f2tf(w);
    }
    if (t < HH) {
        float sb = __ldg(Lb + t);
        #pragma unroll 8
        for (int m = 0; m < HH; m++) sb += __ldg(b + m) * __ldg(L + m * HH + t);
        g_bv[g][t] = sb;
    }
}

// ---------------- degree + dinv ----------------------------------------------

__global__ void k_deg_all(const int* __restrict__ ei) {
    int t = blockIdx.x / DEG_BPS;
    unsigned e = (blockIdx.x % DEG_BPS) * 256 + threadIdx.x;
    int d = __ldg(ei + (size_t)t * 2 * EE + EE + e);
    atomicAdd(&g_deg[t * NN + d], 1);
}

__global__ void k_dinv_all() {
    unsigned i = blockIdx.x * blockDim.x + threadIdx.x;
    if (i < (unsigned)TOTN) g_dinv[i] = rsqrtf((float)(g_deg[i] + 1));
}

// ---------------- exclusive scan ----------------------------------------------

__global__ void k_scan_block() {
    __shared__ int sh[256];
    int tid = threadIdx.x;
    int i = blockIdx.x * 256 + tid;
    int v = (i < TOTN) ? g_deg[i] : 0;
    sh[tid] = v;
    __syncthreads();
    #pragma unroll
    for (int off = 1; off < 256; off <<= 1) {
        int tv = (tid >= off) ? sh[tid - off] : 0;
        __syncthreads();
        sh[tid] += tv;
        __syncthreads();
    }
    if (i < TOTN) g_roff[i] = sh[tid] - v;
    if (tid == 255) g_bsum[blockIdx.x] = sh[255];
}

__global__ void k_scan_aux() {
    __shared__ int part[256];
    int tid = threadIdx.x;
    int start = tid * AUX_PER_THREAD;
    int loc[AUX_PER_THREAD];
    int vv [AUX_PER_THREAD];
    int sum = 0;
    #pragma unroll
    for (int j = 0; j < AUX_PER_THREAD; j++) {
        int idx = start + j;
        int v = (idx < SCAN_BLOCKS) ? g_bsum[idx] : 0;
        vv[j] = v;
        sum += v;
        loc[j] = sum;
    }
    part[tid] = sum;
    __syncthreads();
    #pragma unroll
    for (int off = 1; off < 256; off <<= 1) {
        int tv = (tid >= off) ? part[tid - off] : 0;
        __syncthreads();
        part[tid] += tv;
        __syncthreads();
    }
    int prev = (tid > 0) ? part[tid - 1] : 0;
    #pragma unroll
    for (int j = 0; j < AUX_PER_THREAD; j++) {
        int idx = start + j;
        if (idx < SCAN_BLOCKS) g_bsum[idx] = prev + loc[j] - vv[j];
    }
}

__global__ void k_scan_add() {
    int i = blockIdx.x * 256 + threadIdx.x;
    if (i < TOTN) g_roff[i] += g_bsum[blockIdx.x];
}

// ---------------- CSR placement (packed src + norm) -------------------------

__global__ void k_place(const int* __restrict__ ei) {
    int t = blockIdx.x / PLACE_BPS;
    unsigned e = (blockIdx.x % PLACE_BPS) * 256 + threadIdx.x;
    const int* base = ei + (size_t)t * 2 * EE;
    int s = __ldg(base + e);
    int d = __ldg(base + EE + e);
    int i = t * NN + d;
    int pos = g_roff[i] + atomicAdd(&g_cur[i], 1);
    float w = __ldg(&g_dinv[t * NN + s]) * __ldg(&g_dinv[i]);
    g_csrp[pos] = (u64)(unsigned)s | ((u64)__float_as_uint(w) << 32);
}

// ---------------- pull-mode gather (R10 version, unchanged) -----------------

__global__ void k_gather(const float* __restrict__ xs) {
    unsigned idx = blockIdx.x * 256 + threadIdx.x;   // < TOTN*8
    unsigned nf = idx >> 3;          // flat (t,node)
    unsigned c  = idx & 7u;
    int t = nf / NN;
    int node = nf - t * NN;
    const float* x = xs + (size_t)t * NN * FF;

    float dd = g_dinv[nf];
    float4 acc = __ldg(reinterpret_cast<const float4*>(x + (size_t)node * FF) + c);
    float d2 = dd * dd;
    acc.x *= d2; acc.y *= d2; acc.z *= d2; acc.w *= d2;

    int beg = g_roff[nf];
    int end = beg + g_deg[nf];
    for (int p = beg; p < end; p++) {
        u64 rec = __ldg(g_csrp + p);
        int s = (int)(unsigned)(rec & 0xffffffffULL);
        float ns = __uint_as_float((unsigned)(rec >> 32));
        float4 v = __ldg(reinterpret_cast<const float4*>(x + (size_t)s * FF) + c);
        acc.x = fmaf(v.x, ns, acc.x);
        acc.y = fmaf(v.y, ns, acc.y);
        acc.z = fmaf(v.z, ns, acc.z);
        acc.w = fmaf(v.w, ns, acc.w);
    }
    reinterpret_cast<float4*>(g_aggx + (size_t)nf * FF)[c] = acc;
}

// ---------------- GRU gates on tensor cores (mma.sync tf32) -----------------
// Block: 256 thr = 8 warps, 128 nodes. Warp: 16 nodes (rows g4, g4+8 per frag).
// Three phases (Z, R, Htilde), each a [16 x 64 x 96] GEMM per warp built from
// m16n8k8 tf32 mma. A = [aggx | h] (phases Z,R) or [aggx | h*R] (phase H).

__global__ void __launch_bounds__(256) k_gates_mma(int t) {
    extern __shared__ unsigned smem_u[];
    unsigned* Bsh = smem_u;                                        // [KK][BSH_W]
    unsigned* HRw = smem_u + KK * BSH_W + (threadIdx.x >> 5) * (16 * HR_W);

    int tid = threadIdx.x;
    int lane = tid & 31;
    int g4 = lane >> 2, t4 = lane & 3;
    int warp = tid >> 5;

    const float* aggx_t = g_aggx + (size_t)t * NN * FF;

    int node0 = blockIdx.x * NPB + warp * 16;
    int r0 = node0 + g4;
    int r1 = r0 + 8;
    bool v0 = r0 < NN, v1 = r1 < NN;

    // resident aggx A-fragments (k-steps 0..3)
    unsigned Aa[4][4];
    #pragma unroll
    for (int kk = 0; kk < 4; kk++) {
        int c0 = kk * 8 + t4, c1 = c0 + 4;
        Aa[kk][0] = f2tf(v0 ? __ldg(aggx_t + (size_t)r0 * FF + c0) : 0.f);
        Aa[kk][1] = f2tf(v1 ? __ldg(aggx_t + (size_t)r1 * FF + c0) : 0.f);
        Aa[kk][2] = f2tf(v0 ? __ldg(aggx_t + (size_t)r0 * FF + c1) : 0.f);
        Aa[kk][3] = f2tf(v1 ? __ldg(aggx_t + (size_t)r1 * FF + c1) : 0.f);
    }

    float Z[8][4];
    float acc[8][4];

    for (int gate = 0; gate < 3; gate++) {
        __syncthreads();                       // protect Bsh (and HRw ordering)
        // stage this gate's weight panel
        const unsigned* Wg = &g_Wmma[gate][0][0];
        for (int i = tid; i < KK * HH / 2; i += 256) {
            int k = i >> 5, j = (i & 31) * 2;
            uint2 w = *reinterpret_cast<const uint2*>(Wg + k * HH + j);
            Bsh[k * BSH_W + j]     = w.x;
            Bsh[k * BSH_W + j + 1] = w.y;
        }
        __syncthreads();

        #pragma unroll
        for (int nt = 0; nt < 8; nt++)
            #pragma unroll
            for (int q = 0; q < 4; q++) acc[nt][q] = 0.f;

        #pragma unroll
        for (int kk = 0; kk < 12; kk++) {
            unsigned a0, a1, a2, a3;
            if (kk < 4) {
                a0 = Aa[kk][0]; a1 = Aa[kk][1]; a2 = Aa[kk][2]; a3 = Aa[kk][3];
            } else if (gate < 2) {
                int c0 = (kk - 4) * 8 + t4, c1 = c0 + 4;
                a0 = f2tf(v0 ? __ldg(g_h + (size_t)r0 * HH + c0) : 0.f);
                a1 = f2tf(v1 ? __ldg(g_h + (size_t)r1 * HH + c0) : 0.f);
                a2 = f2tf(v0 ? __ldg(g_h + (size_t)r0 * HH + c1) : 0.f);
                a3 = f2tf(v1 ? __ldg(g_h + (size_t)r1 * HH + c1) : 0.f);
            } else {
                int c0 = (kk - 4) * 8 + t4, c1 = c0 + 4;
                a0 = HRw[g4 * HR_W + c0];
                a1 = HRw[(g4 + 8) * HR_W + c0];
                a2 = HRw[g4 * HR_W + c1];
                a3 = HRw[(g4 + 8) * HR_W + c1];
            }
            #pragma unroll
            for (int nt = 0; nt < 8; nt++) {
                unsigned b0 = Bsh[(kk * 8 + t4) * BSH_W + nt * 8 + g4];
                unsigned b1 = Bsh[(kk * 8 + t4 + 4) * BSH_W + nt * 8 + g4];
                mma8(acc[nt], a0, a1, a2, a3, b0, b1);
            }
        }

        if (gate == 0) {
            #pragma unroll
            for (int nt = 0; nt < 8; nt++) {
                int col = nt * 8 + 2 * t4;
                float ba = __ldg(&g_bv[0][col]), bb = __ldg(&g_bv[0][col + 1]);
                Z[nt][0] = sigmoidf_(acc[nt][0] + ba);
                Z[nt][1] = sigmoidf_(acc[nt][1] + bb);
                Z[nt][2] = sigmoidf_(acc[nt][2] + ba);
                Z[nt][3] = sigmoidf_(acc[nt][3] + bb);
            }
        } else if (gate == 1) {
            #pragma unroll
            for (int nt = 0; nt < 8; nt++) {
                int col = nt * 8 + 2 * t4;
                float ba = __ldg(&g_bv[1][col]), bb = __ldg(&g_bv[1][col + 1]);
                float h00 = v0 ? g_h[(size_t)r0 * HH + col]     : 0.f;
                float h01 = v0 ? g_h[(size_t)r0 * HH + col + 1] : 0.f;
                float h10 = v1 ? g_h[(size_t)r1 * HH + col]     : 0.f;
                float h11 = v1 ? g_h[(size_t)r1 * HH + col + 1] : 0.f;
                HRw[g4 * HR_W + col]           = f2tf(h00 * sigmoidf_(acc[nt][0] + ba));
                HRw[g4 * HR_W + col + 1]       = f2tf(h01 * sigmoidf_(acc[nt][1] + bb));
                HRw[(g4 + 8) * HR_W + col]     = f2tf(h10 * sigmoidf_(acc[nt][2] + ba));
                HRw[(g4 + 8) * HR_W + col + 1] = f2tf(h11 * sigmoidf_(acc[nt][3] + bb));
            }
        } else {
            #pragma unroll
            for (int nt = 0; nt < 8; nt++) {
                int col = nt * 8 + 2 * t4;
                float ba = __ldg(&g_bv[2][col]), bb = __ldg(&g_bv[2][col + 1]);
                float Ht0 = tanhf(acc[nt][0] + ba);
                float Ht1 = tanhf(acc[nt][1] + bb);
                float Ht2 = tanhf(acc[nt][2] + ba);
                float Ht3 = tanhf(acc[nt][3] + bb);
                if (v0) {
                    float h00 = g_h[(size_t)r0 * HH + col];
                    float h01 = g_h[(size_t)r0 * HH + col + 1];
                    float o0 = Z[nt][0] * h00 + (1.f - Z[nt][0]) * Ht0;
                    float o1 = Z[nt][1] * h01 + (1.f - Z[nt][1]) * Ht1;
                    *reinterpret_cast<float2*>(g_h + (size_t)r0 * HH + col) = make_float2(o0, o1);
                }
                if (v1) {
                    float h10 = g_h[(size_t)r1 * HH + col];
                    float h11 = g_h[(size_t)r1 * HH + col + 1];
                    float o2 = Z[nt][2] * h10 + (1.f - Z[nt][2]) * Ht2;
                    float o3 = Z[nt][3] * h11 + (1.f - Z[nt][3]) * Ht3;
                    *reinterpret_cast<float2*>(g_h + (size_t)r1 * HH + col) = make_float2(o2, o3);
                }
            }
        }
    }
}

__global__ void k_out(const float* __restrict__ oW, const float* __restrict__ ob,
                      float* __restrict__ out) {
    unsigned idx = blockIdx.x * blockDim.x + threadIdx.x;
    if (idx >= (unsigned)(NN * OUTC)) return;
    int i = idx >> 4, j = idx & 15;
    const float* hr = g_h + (size_t)i * HH;
    float acc = __ldg(ob + j);
    #pragma unroll
    for (int k = 0; k < HH; k++) acc += hr[k] * __ldg(oW + k * OUTC + j);
    out[idx] = acc;
}

// ---------------- launch ----------------------------------------------------
extern "C" void kernel_launch(void* const* d_in, const int* in_sizes, int n_in,
                              void* d_out, int out_size) {
    const float* xs  = (const float*)d_in[0];
    const int*   ei  = (const int*)  d_in[1];
    const float* Wz  = (const float*)d_in[2];
    const float* bz  = (const float*)d_in[3];
    const float* Wr  = (const float*)d_in[4];
    const float* br  = (const float*)d_in[5];
    const float* Wh  = (const float*)d_in[6];
    const float* bh  = (const float*)d_in[7];
    const float* Lz  = (const float*)d_in[8];
    const float* Lzb = (const float*)d_in[9];
    const float* Lr  = (const float*)d_in[10];
    const float* Lrb = (const float*)d_in[11];
    const float* Lh  = (const float*)d_in[12];
    const float* Lhb = (const float*)d_in[13];
    const float* oW  = (const float*)d_in[14];
    const float* ob  = (const float*)d_in[15];
    float* out = (float*)d_out;

    cudaFuncSetAttribute(k_gates_mma, cudaFuncAttributeMaxDynamicSharedMemorySize,
                         SMEM_GATES);

    k_prep<<<3, 256>>>(Wz, bz, Wr, br, Wh, bh, Lz, Lzb, Lr, Lrb, Lh, Lhb);
    k_clear_h<<<(NN * HH + 255) / 256, 256>>>();
    k_clear_int2<<<SCAN_BLOCKS, 256>>>();

    k_deg_all<<<TT * DEG_BPS, 256>>>(ei);
    k_dinv_all<<<SCAN_BLOCKS, 256>>>();
    k_scan_block<<<SCAN_BLOCKS, 256>>>();
    k_scan_aux<<<1, 256>>>();
    k_scan_add<<<SCAN_BLOCKS, 256>>>();
    k_place<<<TT * PLACE_BPS, 256>>>(ei);
    k_gather<<<GATH_BPS, 256>>>(xs);

    for (int t = 0; t < TT; t++)
        k_gates_mma<<<GATE_BLOCKS, 256, SMEM_GATES>>>(t);

    k_out<<<(NN * OUTC + 255) / 256, 256>>>(oW, ob, out);
}